// round 6
// baseline (speedup 1.0000x reference)
#include <cuda_runtime.h>
#include <cstdint>

#define H 4096
#define NUM_LAYERS 8
#define ROWS 8                        // rows per block (contiguous 128 KB of W)
#define THREADS 256                   // 8 warps
#define ROW_BYTES (H * 4)             // 16 KB
#define STAGE_BYTES (2 * ROW_BYTES)   // 32 KB: one row-pair
#define STAGES 4                      // 4 pairs = whole block, single pass

// Dynamic smem layout (byte offsets)
#define SMEM_X 0                                    // x vector: 16 KB
#define SMEM_W (16384)                              // 4 stages x 32 KB = 128 KB
#define SMEM_MBAR (SMEM_W + STAGES * STAGE_BYTES)   // 4 mbarriers
#define SMEM_PART (SMEM_MBAR + STAGES * 8)          // 32 float partials
#define SMEM_TOTAL (SMEM_PART + 32 * 4 + 16)

// Ping-pong hidden-state buffers (allocation-free scratch).
__device__ float g_h[2][H];

__device__ __forceinline__ uint32_t smem_u32(const void* p) {
    uint32_t a;
    asm("{ .reg .u64 t; cvta.to.shared.u64 t, %1; cvt.u32.u64 %0, t; }"
        : "=r"(a) : "l"(p));
    return a;
}
__device__ __forceinline__ void mbar_init(uint32_t mbar, uint32_t count) {
    asm volatile("mbarrier.init.shared.b64 [%0], %1;" :: "r"(mbar), "r"(count) : "memory");
}
__device__ __forceinline__ void mbar_expect_tx(uint32_t mbar, uint32_t bytes) {
    asm volatile("mbarrier.arrive.expect_tx.shared.b64 _, [%0], %1;"
                 :: "r"(mbar), "r"(bytes) : "memory");
}
__device__ __forceinline__ void mbar_wait(uint32_t mbar, uint32_t parity) {
    asm volatile(
        "{\n\t.reg .pred P;\n\t"
        "W_%=:\n\t"
        "mbarrier.try_wait.parity.acquire.cta.shared::cta.b64 P, [%0], %1, 0x989680;\n\t"
        "@P bra D_%=;\n\t"
        "bra W_%=;\n\t"
        "D_%=:\n\t}"
        :: "r"(mbar), "r"(parity) : "memory");
}
__device__ __forceinline__ void bulk_cp(uint32_t dst_smem, const void* src_gmem,
                                        uint32_t bytes, uint32_t mbar) {
    asm volatile(
        "cp.async.bulk.shared::cluster.global.mbarrier::complete_tx::bytes "
        "[%0], [%1], %2, [%3];"
        :: "r"(dst_smem), "l"(src_gmem), "r"(bytes), "r"(mbar) : "memory");
}

// GEMV, DRAM-locality-first: each block owns 8 CONTIGUOUS rows (128 KB slab of
// W). The whole slab is prefetched at block start via cp.async.bulk in
// sequential 16 KB copies (512 long sequential DRAM streams chip-wide instead
// of 4096 interleaved ones -> HBM page-hit runs). Compute is a single pass
// over 4 row-pair stages; 4 warps split-K each row from smem.
template <bool TANH, bool HAS_B1>
__global__ void __launch_bounds__(THREADS)
gemv_kernel(const float* __restrict__ W,
            const float* __restrict__ b0,
            const float* __restrict__ b1,
            const float* __restrict__ h_in,
            float* __restrict__ h_out) {
    extern __shared__ char smem[];
    const uint32_t sbase = smem_u32(smem);

    const int warp = threadIdx.x >> 5;
    const int lane = threadIdx.x & 31;
    const int row0 = blockIdx.x * ROWS;

    // Init mbarriers, then issue the ENTIRE 128 KB slab immediately
    // (8 sequential 16 KB bulk copies -> one long DRAM stream per block).
    if (threadIdx.x == 0) {
        #pragma unroll
        for (int s = 0; s < STAGES; s++)
            mbar_init(sbase + SMEM_MBAR + s * 8, 1);
        asm volatile("fence.proxy.async.shared::cta;" ::: "memory");
        #pragma unroll
        for (int s = 0; s < STAGES; s++) {
            const uint32_t mbar = sbase + SMEM_MBAR + s * 8;
            mbar_expect_tx(mbar, STAGE_BYTES);
            bulk_cp(sbase + SMEM_W + s * STAGE_BYTES,
                    W + (size_t)(row0 + 2 * s) * H, ROW_BYTES, mbar);
            bulk_cp(sbase + SMEM_W + s * STAGE_BYTES + ROW_BYTES,
                    W + (size_t)(row0 + 2 * s + 1) * H, ROW_BYTES, mbar);
        }
    }

    // Stage the x vector (16 KB) into shared memory while TMA streams W.
    {
        const float4* xg = reinterpret_cast<const float4*>(h_in);
        float4* xs = reinterpret_cast<float4*>(smem + SMEM_X);
        #pragma unroll
        for (int i = threadIdx.x; i < H / 4; i += THREADS)
            xs[i] = xg[i];
    }
    __syncthreads();

    // warp -> (row-in-pair q, K-quarter k)
    const int q = warp >> 2;          // 0..1
    const int k = warp & 3;           // 0..3
    const float4* xq = reinterpret_cast<const float4*>(smem + SMEM_X) + k * (H / 4 / 4);
    float* partial = reinterpret_cast<float*>(smem + SMEM_PART);

    #pragma unroll
    for (int s = 0; s < STAGES; s++) {
        mbar_wait(sbase + SMEM_MBAR + s * 8, 0);

        const float4* wr = reinterpret_cast<const float4*>(
            smem + SMEM_W + s * STAGE_BYTES + q * ROW_BYTES) + k * (H / 4 / 4);

        float a0 = 0.f, a1 = 0.f;
        #pragma unroll
        for (int j = 0; j < 8; j += 2) {
            float4 w0 = wr[lane + (j + 0) * 32];
            float4 x0 = xq[lane + (j + 0) * 32];
            float4 w1 = wr[lane + (j + 1) * 32];
            float4 x1 = xq[lane + (j + 1) * 32];
            a0 += w0.x * x0.x + w0.y * x0.y + w0.z * x0.z + w0.w * x0.w;
            a1 += w1.x * x1.x + w1.y * x1.y + w1.z * x1.z + w1.w * x1.w;
        }
        float acc = a0 + a1;
        #pragma unroll
        for (int off = 16; off; off >>= 1)
            acc += __shfl_down_sync(0xffffffffu, acc, off);
        if (lane == 0)
            partial[s * 8 + warp] = acc;
    }
    __syncthreads();

    // Threads 0..7 each finalize one row: row j = 2*s + q, s=j>>1, q=j&1.
    if (threadIdx.x < ROWS) {
        const int j = threadIdx.x;
        const int s = j >> 1, qq = j & 1;
        const float* p = partial + s * 8 + qq * 4;
        float v = (p[0] + p[1]) + (p[2] + p[3]);
        const int row = row0 + j;
        v += b0[row];
        if (HAS_B1) v += b1[row];
        h_out[row] = TANH ? tanhf(v) : v;
    }
}

extern "C" void kernel_launch(void* const* d_in, const int* in_sizes, int n_in,
                              void* d_out, int out_size) {
    const float* x    = (const float*)d_in[0];  // [1, H]
    const float* Wxh  = (const float*)d_in[1];  // [L, H, H]
    const float* bxh  = (const float*)d_in[2];  // [L, H]
    // d_in[3] = Whh — multiplied by a zero vector in the reference; never read.
    const float* bhh  = (const float*)d_in[4];  // [L, H]
    const float* fc_w = (const float*)d_in[5];  // [H, H]
    const float* fc_b = (const float*)d_in[6];  // [H]
    float* out = (float*)d_out;

    cudaFuncSetAttribute(gemv_kernel<true, true>,
                         cudaFuncAttributeMaxDynamicSharedMemorySize, SMEM_TOTAL);
    cudaFuncSetAttribute(gemv_kernel<false, false>,
                         cudaFuncAttributeMaxDynamicSharedMemorySize, SMEM_TOTAL);

    float* hbuf = nullptr;
    cudaGetSymbolAddress((void**)&hbuf, g_h);
    float* h0 = hbuf;      // g_h[0]
    float* h1 = hbuf + H;  // g_h[1]

    const dim3 grid(H / ROWS);   // 512 blocks
    const dim3 block(THREADS);   // 256 threads

    const float* cur = x;
    float* nxt = h0;
    for (int i = 0; i < NUM_LAYERS; i++) {
        gemv_kernel<true, true><<<grid, block, SMEM_TOTAL>>>(
            Wxh + (size_t)i * H * H, bxh + (size_t)i * H, bhh + (size_t)i * H,
            cur, nxt);
        cur = nxt;
        nxt = (nxt == h0) ? h1 : h0;
    }
    // Final linear layer: no tanh, single bias.
    gemv_kernel<false, false><<<grid, block, SMEM_TOTAL>>>(fc_w, fc_b, nullptr, cur, out);
}

// round 7
// speedup vs baseline: 1.2219x; 1.2219x over previous
#include <cuda_runtime.h>
#include <cstdint>

#define H 4096
#define NUM_LAYERS 8
#define ROWS 8                 // rows per block: 4 via LDG, 4 via TMA
#define THREADS 256            // 8 warps
#define ROW_BYTES (H * 4)      // 16 KB

// Dynamic smem layout (byte offsets)
#define SMEM_X 0                         // x vector: 16 KB
#define SMEM_WT 16384                    // TMA rows 4..7: 64 KB
#define SMEM_MBAR (SMEM_WT + 4 * ROW_BYTES)
#define SMEM_TOTAL (SMEM_MBAR + 2 * 8 + 16)   // ~80 KB -> 2 blocks/SM

// Ping-pong hidden-state buffers (allocation-free scratch).
__device__ float g_h[2][H];

__device__ __forceinline__ uint32_t smem_u32(const void* p) {
    uint32_t a;
    asm("{ .reg .u64 t; cvta.to.shared.u64 t, %1; cvt.u32.u64 %0, t; }"
        : "=r"(a) : "l"(p));
    return a;
}
__device__ __forceinline__ void mbar_init(uint32_t mbar, uint32_t count) {
    asm volatile("mbarrier.init.shared.b64 [%0], %1;" :: "r"(mbar), "r"(count) : "memory");
}
__device__ __forceinline__ void mbar_expect_tx(uint32_t mbar, uint32_t bytes) {
    asm volatile("mbarrier.arrive.expect_tx.shared.b64 _, [%0], %1;"
                 :: "r"(mbar), "r"(bytes) : "memory");
}
__device__ __forceinline__ void mbar_wait(uint32_t mbar, uint32_t parity) {
    asm volatile(
        "{\n\t.reg .pred P;\n\t"
        "W_%=:\n\t"
        "mbarrier.try_wait.parity.acquire.cta.shared::cta.b64 P, [%0], %1, 0x989680;\n\t"
        "@P bra D_%=;\n\t"
        "bra W_%=;\n\t"
        "D_%=:\n\t}"
        :: "r"(mbar), "r"(parity) : "memory");
}
__device__ __forceinline__ void bulk_cp(uint32_t dst_smem, const void* src_gmem,
                                        uint32_t bytes, uint32_t mbar) {
    asm volatile(
        "cp.async.bulk.shared::cluster.global.mbarrier::complete_tx::bytes "
        "[%0], [%1], %2, [%3];"
        :: "r"(dst_smem), "l"(src_gmem), "r"(bytes), "r"(mbar) : "memory");
}

// Hybrid dual-path GEMV. Per block of 8 contiguous rows:
//   rows 0-3: warps 0-3 stream weights directly via LDG.128 batches of 8
//             (saturates the per-SM L1tex wavefront queue, ~32 KB in flight)
//   rows 4-7: streamed gmem->smem via two 32 KB cp.async.bulk copies
//             (separate in-flight pool, bypasses the L1tex queue),
//             consumed by warps 4-7.
// The two engines together exceed the per-SM BW*latency requirement that
// caps single-path kernels at ~4.5 TB/s.
template <bool TANH, bool HAS_B1>
__global__ void __launch_bounds__(THREADS, 2)
gemv_kernel(const float* __restrict__ W,
            const float* __restrict__ b0,
            const float* __restrict__ b1,
            const float* __restrict__ h_in,
            float* __restrict__ h_out) {
    extern __shared__ char smem[];
    const uint32_t sbase = smem_u32(smem);

    const int warp = threadIdx.x >> 5;
    const int lane = threadIdx.x & 31;
    const int row0 = blockIdx.x * ROWS;

    // Thread 0: arm mbarriers and kick off the TMA stream for rows 4..7
    // (two contiguous 32 KB copies) before anything else.
    if (threadIdx.x == 0) {
        mbar_init(sbase + SMEM_MBAR + 0, 1);
        mbar_init(sbase + SMEM_MBAR + 8, 1);
        asm volatile("fence.proxy.async.shared::cta;" ::: "memory");
        #pragma unroll
        for (int s = 0; s < 2; s++) {
            const uint32_t mbar = sbase + SMEM_MBAR + s * 8;
            mbar_expect_tx(mbar, 2 * ROW_BYTES);
            bulk_cp(sbase + SMEM_WT + s * 2 * ROW_BYTES,
                    W + (size_t)(row0 + 4 + 2 * s) * H,
                    2 * ROW_BYTES, mbar);
        }
    }

    // Stage the x vector (16 KB) into shared memory.
    {
        const float4* xg = reinterpret_cast<const float4*>(h_in);
        float4* xs = reinterpret_cast<float4*>(smem + SMEM_X);
        #pragma unroll
        for (int i = threadIdx.x; i < H / 4; i += THREADS)
            xs[i] = xg[i];
    }
    __syncthreads();

    const float4* sh4 = reinterpret_cast<const float4*>(smem + SMEM_X);
    float acc[4] = {0.f, 0.f, 0.f, 0.f};
    int row;

    if (warp < 4) {
        // ---- LDG path: row0 + warp, weights straight from gmem ----
        row = row0 + warp;
        const float4* Wr = reinterpret_cast<const float4*>(W + (size_t)row * H);
        #pragma unroll
        for (int b = 0; b < 4; b++) {
            float4 w[8];
            #pragma unroll
            for (int j = 0; j < 8; j++)          // 8 independent LDG.128
                w[j] = Wr[lane + (b * 8 + j) * 32];
            #pragma unroll
            for (int j = 0; j < 8; j++) {
                float4 xv = sh4[lane + (b * 8 + j) * 32];
                acc[j & 3] += w[j].x * xv.x + w[j].y * xv.y
                            + w[j].z * xv.z + w[j].w * xv.w;
            }
        }
    } else {
        // ---- TMA path: row0 + warp, weights from smem stage ----
        row = row0 + warp;
        const int s = (warp - 4) >> 1;           // stage: warps 4,5 -> 0; 6,7 -> 1
        mbar_wait(sbase + SMEM_MBAR + s * 8, 0);
        const float4* Wr = reinterpret_cast<const float4*>(
            smem + SMEM_WT + (warp - 4) * ROW_BYTES);
        #pragma unroll
        for (int b = 0; b < 8; b++) {
            #pragma unroll
            for (int j = 0; j < 4; j++) {
                float4 w4 = Wr[lane + (b * 4 + j) * 32];
                float4 xv = sh4[lane + (b * 4 + j) * 32];
                acc[j] += w4.x * xv.x + w4.y * xv.y
                        + w4.z * xv.z + w4.w * xv.w;
            }
        }
    }

    float acc_all = (acc[0] + acc[1]) + (acc[2] + acc[3]);
    #pragma unroll
    for (int off = 16; off; off >>= 1)
        acc_all += __shfl_down_sync(0xffffffffu, acc_all, off);

    if (lane == 0) {
        float v = acc_all + b0[row];
        if (HAS_B1) v += b1[row];
        h_out[row] = TANH ? tanhf(v) : v;
    }
}

extern "C" void kernel_launch(void* const* d_in, const int* in_sizes, int n_in,
                              void* d_out, int out_size) {
    const float* x    = (const float*)d_in[0];  // [1, H]
    const float* Wxh  = (const float*)d_in[1];  // [L, H, H]
    const float* bxh  = (const float*)d_in[2];  // [L, H]
    // d_in[3] = Whh — multiplied by a zero vector in the reference; never read.
    const float* bhh  = (const float*)d_in[4];  // [L, H]
    const float* fc_w = (const float*)d_in[5];  // [H, H]
    const float* fc_b = (const float*)d_in[6];  // [H]
    float* out = (float*)d_out;

    cudaFuncSetAttribute(gemv_kernel<true, true>,
                         cudaFuncAttributeMaxDynamicSharedMemorySize, SMEM_TOTAL);
    cudaFuncSetAttribute(gemv_kernel<false, false>,
                         cudaFuncAttributeMaxDynamicSharedMemorySize, SMEM_TOTAL);

    float* hbuf = nullptr;
    cudaGetSymbolAddress((void**)&hbuf, g_h);
    float* h0 = hbuf;      // g_h[0]
    float* h1 = hbuf + H;  // g_h[1]

    const dim3 grid(H / ROWS);   // 512 blocks
    const dim3 block(THREADS);   // 256 threads

    const float* cur = x;
    float* nxt = h0;
    for (int i = 0; i < NUM_LAYERS; i++) {
        gemv_kernel<true, true><<<grid, block, SMEM_TOTAL>>>(
            Wxh + (size_t)i * H * H, bxh + (size_t)i * H, bhh + (size_t)i * H,
            cur, nxt);
        cur = nxt;
        nxt = (nxt == h0) ? h1 : h0;
    }
    // Final linear layer: no tanh, single bias.
    gemv_kernel<false, false><<<grid, block, SMEM_TOTAL>>>(fc_w, fc_b, nullptr, cur, out);
}

// round 8
// speedup vs baseline: 1.3309x; 1.0892x over previous
#include <cuda_runtime.h>
#include <cstdint>

#define H 4096
#define NUM_LAYERS 8
#define NBLOCKS 256
#define NTHREADS 512          // 16 warps -> 4096 warps total == one per row

// Ping-pong hidden-state buffers (allocation-free scratch).
__device__ float g_h[2][H];

// Software grid-barrier state (monotonic across graph replays).
__device__ unsigned g_bar_count = 0;
__device__ unsigned g_bar_phase = 0;

// Grid-wide barrier. Safe because all NBLOCKS are co-resident
// (NBLOCKS=256 <= 148 SMs * 2 blocks, enforced by __launch_bounds__(512,2)).
// Release: block-wide bar.sync chains all threads' writes to thread 0,
// whose __threadfence() (gpu scope, cumulative) publishes them.
__device__ __forceinline__ void grid_barrier() {
    __syncthreads();
    if (threadIdx.x == 0) {
        const unsigned target = *(volatile unsigned*)&g_bar_phase + 1;
        __threadfence();
        const unsigned old = atomicAdd(&g_bar_count, 1);
        if (old == NBLOCKS - 1) {
            *(volatile unsigned*)&g_bar_count = 0;
            __threadfence();
            atomicAdd(&g_bar_phase, 1);
        } else {
            while (*(volatile unsigned*)&g_bar_phase < target)
                __nanosleep(64);
        }
        __threadfence();
    }
    __syncthreads();
}

// One warp computes dot(W[row,:], x_smem) with the R1-proven batch-4
// LDG.128 schedule (4 independent loads in flight, ~46 regs).
__device__ __forceinline__ float row_dot(const float* __restrict__ W,
                                         const float4* __restrict__ sh4,
                                         int row, int lane) {
    const float4* Wr = reinterpret_cast<const float4*>(W + (size_t)row * H);
    float acc[4] = {0.f, 0.f, 0.f, 0.f};
    #pragma unroll
    for (int i = 0; i < 32; i += 4) {
        float4 w[4];
        #pragma unroll
        for (int j = 0; j < 4; j++)
            w[j] = Wr[lane + (i + j) * 32];
        #pragma unroll
        for (int j = 0; j < 4; j++) {
            float4 xv = sh4[lane + (i + j) * 32];
            acc[j] += w[j].x * xv.x + w[j].y * xv.y
                    + w[j].z * xv.z + w[j].w * xv.w;
        }
    }
    float a = (acc[0] + acc[1]) + (acc[2] + acc[3]);
    #pragma unroll
    for (int off = 16; off; off >>= 1)
        a += __shfl_down_sync(0xffffffffu, a, off);
    return a;
}

// Whole network in one persistent kernel: 8 tanh layers + final fc.
// Exactly one warp per output row per layer (4096 warps); layers separated
// by a software grid barrier instead of kernel launches (kills launch gaps,
// start ramps, drain tails, and wave quantization).
__global__ void __launch_bounds__(NTHREADS, 2)
rnn_fused_kernel(const float* __restrict__ x,
                 const float* __restrict__ Wxh,
                 const float* __restrict__ bxh,
                 const float* __restrict__ bhh,
                 const float* __restrict__ fc_w,
                 const float* __restrict__ fc_b,
                 float* __restrict__ out) {
    __shared__ float4 sh4[H / 4];   // 16 KB: current input vector

    const int warp = threadIdx.x >> 5;
    const int lane = threadIdx.x & 31;
    const int row  = blockIdx.x * (NTHREADS / 32) + warp;   // 0..4095

    const float* cur = x;

    #pragma unroll 1
    for (int l = 0; l < NUM_LAYERS; l++) {
        // Stage the layer input (16 KB) into shared memory.
        const float4* xg = reinterpret_cast<const float4*>(cur);
        #pragma unroll
        for (int i = threadIdx.x; i < H / 4; i += NTHREADS)
            sh4[i] = xg[i];
        __syncthreads();

        const float a = row_dot(Wxh + (size_t)l * H * H, sh4, row, lane);
        if (lane == 0)
            g_h[l & 1][row] = tanhf(a + bxh[l * H + row] + bhh[l * H + row]);

        grid_barrier();               // publish h before anyone reads it
        cur = g_h[l & 1];
    }

    // Final linear layer (no tanh, single bias) -> d_out.
    {
        const float4* xg = reinterpret_cast<const float4*>(cur);
        #pragma unroll
        for (int i = threadIdx.x; i < H / 4; i += NTHREADS)
            sh4[i] = xg[i];
        __syncthreads();

        const float a = row_dot(fc_w, sh4, row, lane);
        if (lane == 0)
            out[row] = a + fc_b[row];
    }
}

extern "C" void kernel_launch(void* const* d_in, const int* in_sizes, int n_in,
                              void* d_out, int out_size) {
    const float* x    = (const float*)d_in[0];  // [1, H]
    const float* Wxh  = (const float*)d_in[1];  // [L, H, H]
    const float* bxh  = (const float*)d_in[2];  // [L, H]
    // d_in[3] = Whh — multiplied by a zero vector in the reference; never read.
    const float* bhh  = (const float*)d_in[4];  // [L, H]
    const float* fc_w = (const float*)d_in[5];  // [H, H]
    const float* fc_b = (const float*)d_in[6];  // [H]
    float* out = (float*)d_out;

    rnn_fused_kernel<<<NBLOCKS, NTHREADS>>>(x, Wxh, bxh, bhh, fc_w, fc_b, out);
}